// round 12
// baseline (speedup 1.0000x reference)
#include <cuda_runtime.h>
#include <cuda_bf16.h>
#include <cstdint>

// SimCLR supervised-contrastive loss, class-blocked, bf16 mma.sync GEMM.
// (tcgen05 unavailable: harness emits PTX .target sm_103 without 'a'.)
// Pipeline (3 launches):
//  k_sort  - fused hist/scan/scatter/zero + active-tile work list, 1 block
//  k_gp    - gather-to-bf16 (class-sorted) + positive-pair reduction
//  k_gemm  - persistent blocks, DYNAMIC work stealing over tile list,
//            cp.async 3-stage BK=64 mma.sync, symmetric row+col sums;
//            LAST finishing block computes the final log-reduce scalar.

#define NB 8192
#define BHALF 4096
#define D 512
#define D4 (D/4)
#define NC 7
#define TILE 128
#define NTILE (NB/TILE)
#define NPAIR (NTILE*(NTILE+1)/2)   // 2080
#define INV_T 2.0f
#define GEMM_GRID 296

// ---- scratch (__device__ globals; no allocation) ----
__device__ __nv_bfloat16 g_Gh[NB * D];   // class-sorted rows, bf16 (8 MB)
__device__ int   g_perm[NB];
__device__ int   g_labp[NB];
__device__ float g_denom[NB];
__device__ float g_sums[2];
__device__ int   g_ntiles;
__device__ int   g_tiles[NPAIR];
__device__ int   g_wq;      // work-stealing ticket
__device__ int   g_done;    // finished-block counter

// ---------------------------------------------------------------------------
// k_sort: one block, 1024 threads. Stable counting sort of 8192 labels into
// 7 classes via warp-shuffle scans; zeroes scratch; builds active-tile list.
__global__ __launch_bounds__(1024) void k_sort(const int* __restrict__ labels) {
    __shared__ int swtot[NC][32];
    __shared__ int swex[NC][32];
    __shared__ int sctot[NC];
    __shared__ int sbase[NC];
    __shared__ int scnt;
    const int t = threadIdx.x, lane = t & 31, wid = t >> 5;

    int lab[8];
    int cnt[NC];
#pragma unroll
    for (int c = 0; c < NC; c++) cnt[c] = 0;
#pragma unroll
    for (int j = 0; j < 8; j++) {
        lab[j] = labels[t * 8 + j];
#pragma unroll
        for (int c = 0; c < NC; c++) cnt[c] += (lab[j] == c);
    }
    // warp-inclusive scan per class
    int inc[NC];
#pragma unroll
    for (int c = 0; c < NC; c++) {
        int v = cnt[c];
#pragma unroll
        for (int off = 1; off < 32; off <<= 1) {
            int u = __shfl_up_sync(0xffffffffu, v, off);
            if (lane >= off) v += u;
        }
        inc[c] = v;
        if (lane == 31) swtot[c][wid] = v;
    }
#pragma unroll
    for (int j = 0; j < 8; j++) g_denom[t * 8 + j] = 0.0f;
    if (t < 2) g_sums[t] = 0.0f;
    if (t == 0) { scnt = 0; g_wq = 0; g_done = 0; }
    __syncthreads();
    // cross-warp scan: warp c scans class c over the 32 warp totals
    if (wid < NC) {
        int v = swtot[wid][lane];
        int orig = v;
#pragma unroll
        for (int off = 1; off < 32; off <<= 1) {
            int u = __shfl_up_sync(0xffffffffu, v, off);
            if (lane >= off) v += u;
        }
        swex[wid][lane] = v - orig;
        if (lane == 31) sctot[wid] = v;
    }
    __syncthreads();
    if (t == 0) {
        int run = 0;
#pragma unroll
        for (int c = 0; c < NC; c++) { sbase[c] = run; run += sctot[c]; }
    }
    __syncthreads();
    int off_[NC];
#pragma unroll
    for (int c = 0; c < NC; c++)
        off_[c] = sbase[c] + swex[c][wid] + inc[c] - cnt[c];
    // stable replay (thread covers contiguous elements, threads ordered)
#pragma unroll
    for (int j = 0; j < 8; j++) {
#pragma unroll
        for (int c = 0; c < NC; c++) {
            if (lab[j] == c) {
                int p = off_[c]++;
                g_perm[p] = t * 8 + j;
                g_labp[p] = c;
            }
        }
    }
    __syncthreads();   // g_labp visible block-wide

    // build active-tile list over upper-triangular (i <= j) tile pairs
    for (int idx = t; idx < NPAIR; idx += 1024) {
        int i = 0, rem = idx;
        while (rem >= NTILE - i) { rem -= NTILE - i; i++; }
        int j = i + rem;
        int rlo = g_labp[i * TILE], rhi = g_labp[i * TILE + TILE - 1];
        int clo = g_labp[j * TILE], chi = g_labp[j * TILE + TILE - 1];
        if (!(rhi < clo || chi < rlo)) {
            int p = atomicAdd(&scnt, 1);
            g_tiles[p] = (i << 16) | j;
        }
    }
    __syncthreads();
    if (t == 0) g_ntiles = scnt;
}

// ---------------------------------------------------------------------------
// k_gp: blocks [0,1024) gather rows of `out` into class-sorted bf16 order;
// blocks [1024,1280) compute sum of dot(out_1[i], out_2[i]) -> g_sums[1].
#define GPB 1024
#define POSB 256
__global__ void k_gp(const float* __restrict__ outm,
                     const float* __restrict__ o1,
                     const float* __restrict__ o2) {
    const int b = blockIdx.x, tid = threadIdx.x;
    if (b < GPB) {
        const int n = NB * D / 8;
        for (int i = b * 256 + tid; i < n; i += GPB * 256) {
            int p = i >> 6;
            int q = i & 63;
            const float4* s =
                reinterpret_cast<const float4*>(outm + (size_t)g_perm[p] * D) + q * 2;
            float4 a = s[0], bb = s[1];
            __nv_bfloat162 h0 = __floats2bfloat162_rn(a.x, a.y);
            __nv_bfloat162 h1 = __floats2bfloat162_rn(a.z, a.w);
            __nv_bfloat162 h2 = __floats2bfloat162_rn(bb.x, bb.y);
            __nv_bfloat162 h3 = __floats2bfloat162_rn(bb.z, bb.w);
            uint4 o;
            o.x = *reinterpret_cast<uint32_t*>(&h0);
            o.y = *reinterpret_cast<uint32_t*>(&h1);
            o.z = *reinterpret_cast<uint32_t*>(&h2);
            o.w = *reinterpret_cast<uint32_t*>(&h3);
            reinterpret_cast<uint4*>(g_Gh)[i] = o;
        }
    } else {
        __shared__ float red[256];
        const float4* a = reinterpret_cast<const float4*>(o1);
        const float4* v = reinterpret_cast<const float4*>(o2);
        float s = 0.0f;
        for (int i = (b - GPB) * 256 + tid; i < BHALF * D4; i += POSB * 256) {
            float4 x = a[i], y = v[i];
            s += x.x * y.x + x.y * y.y + x.z * y.z + x.w * y.w;
        }
        red[tid] = s;
        __syncthreads();
        for (int st = 128; st > 0; st >>= 1) {
            if (tid < st) red[tid] += red[tid + st];
            __syncthreads();
        }
        if (tid == 0) atomicAdd(&g_sums[1], red[0]);
    }
}

// ---------------------------------------------------------------------------
// mma.sync helpers
__device__ __forceinline__ uint32_t smem_u32(const void* p) {
    uint32_t a;
    asm("{ .reg .u64 t; cvta.to.shared.u64 t, %1; cvt.u32.u64 %0, t; }" : "=r"(a) : "l"(p));
    return a;
}
__device__ __forceinline__ void ldsm_x4(uint32_t* r, uint32_t addr) {
    asm volatile("ldmatrix.sync.aligned.m8n8.x4.shared.b16 {%0,%1,%2,%3}, [%4];"
                 : "=r"(r[0]), "=r"(r[1]), "=r"(r[2]), "=r"(r[3]) : "r"(addr));
}
__device__ __forceinline__ void mma16816(float* d, const uint32_t* a,
                                         uint32_t b0, uint32_t b1) {
    asm volatile(
        "mma.sync.aligned.m16n8k16.row.col.f32.bf16.bf16.f32 "
        "{%0,%1,%2,%3}, {%4,%5,%6,%7}, {%8,%9}, {%0,%1,%2,%3};"
        : "+f"(d[0]), "+f"(d[1]), "+f"(d[2]), "+f"(d[3])
        : "r"(a[0]), "r"(a[1]), "r"(a[2]), "r"(a[3]), "r"(b0), "r"(b1));
}
// 128x64-bf16 tile (128B rows). XOR swizzle: conflict-free for cp.async 16B
// stores and ldmatrix row fetches.
__device__ __forceinline__ uint32_t sw64(int row, int c16) {
    return (uint32_t)(row * 128 + ((c16 ^ (row & 7)) << 4));
}

#define BK 64
#define NKT (D / BK)          // 8
#define STAGE_BYTES 32768     // A 16KB + B 16KB per stage
#define NSTAGE 3

__global__ void __launch_bounds__(256, 2) k_gemm_mma(float* __restrict__ outp) {
    extern __shared__ char dsm[];
    __shared__ float sdenR[TILE];
    __shared__ float sdenC[TILE];
    __shared__ int   slr[TILE], slc[TILE];
    __shared__ int   swk;
    __shared__ int   sdone;

    const int tid = threadIdx.x;
    const int wid = tid >> 5, lane = tid & 31;
    const int wm = wid >> 2, wn = wid & 3;        // warp tile 64x32
    const uint4* src = reinterpret_cast<const uint4*>(g_Gh);   // 64 uint4/row
    const uint32_t dyn = smem_u32(dsm);

    const int g = lane >> 3, r8 = lane & 7;
    const int row_off = ((g & 1) << 3) + r8;
    const int cch = g >> 1;
    const int qr = lane >> 2, qc = lane & 3;
    const int ntiles = g_ntiles;

    for (;;) {
        if (tid == 0) swk = atomicAdd(&g_wq, 1);
        __syncthreads();
        const int w = swk;
        if (w >= ntiles) break;

        const int item = g_tiles[w];
        const int r0 = (item >> 16) * TILE;
        const int c0 = (item & 0xffff) * TILE;
        const bool offdiag = (c0 != r0);

        if (tid < TILE) {
            slr[tid] = g_labp[r0 + tid];
            slc[tid] = g_labp[c0 + tid];
            sdenR[tid] = 0.0f;
            sdenC[tid] = 0.0f;
        }

        auto issue = [&](int t, int st) {
            const uint32_t sa = dyn + st * STAGE_BYTES;
#pragma unroll
            for (int j = 0; j < 4; j++) {
                int p = j * 256 + tid;
                int row = p >> 3, c16 = p & 7;
                const uint4* gA = src + (size_t)(r0 + row) * 64 + t * 8 + c16;
                const uint4* gB = src + (size_t)(c0 + row) * 64 + t * 8 + c16;
                uint32_t dA = sa + sw64(row, c16);
                uint32_t dB = sa + 16384 + sw64(row, c16);
                asm volatile("cp.async.cg.shared.global [%0], [%1], 16;\n\t"
                             "cp.async.cg.shared.global [%2], [%3], 16;"
                             :: "r"(dA), "l"(gA), "r"(dB), "l"(gB));
            }
            asm volatile("cp.async.commit_group;" ::: "memory");
        };

        issue(0, 0);
        issue(1, 1);

        float acc[4][4][4];
#pragma unroll
        for (int mf = 0; mf < 4; mf++)
#pragma unroll
            for (int nf = 0; nf < 4; nf++)
#pragma unroll
                for (int e = 0; e < 4; e++) acc[mf][nf][e] = 0.0f;

#pragma unroll
        for (int t = 0; t < NKT; t++) {
            if (t < NKT - 1) asm volatile("cp.async.wait_group 1;" ::: "memory");
            else             asm volatile("cp.async.wait_group 0;" ::: "memory");
            __syncthreads();
            if (t + 2 < NKT) issue(t + 2, (t + 2) % NSTAGE);

            const uint32_t sA = dyn + (t % NSTAGE) * STAGE_BYTES;
            const uint32_t sB = sA + 16384;
#pragma unroll
            for (int kc = 0; kc < 4; kc++) {
                uint32_t amat[4][4], bmat[2][4];
                const int c16 = kc * 2 + cch;
#pragma unroll
                for (int mf = 0; mf < 4; mf++)
                    ldsm_x4(amat[mf], sA + sw64(wm * 64 + mf * 16 + row_off, c16));
#pragma unroll
                for (int nb = 0; nb < 2; nb++)
                    ldsm_x4(bmat[nb], sB + sw64(wn * 32 + nb * 16 + row_off, c16));
#pragma unroll
                for (int mf = 0; mf < 4; mf++)
#pragma unroll
                    for (int nf = 0; nf < 4; nf++)
                        mma16816(acc[mf][nf], amat[mf],
                                 bmat[nf >> 1][nf & 1], bmat[nf >> 1][2 + (nf & 1)]);
            }
        }

        // ---- epilogue: mask + exp; row sums always, col sums if offdiag ----
        float colsum[4][2];
#pragma unroll
        for (int nf = 0; nf < 4; nf++) { colsum[nf][0] = 0.0f; colsum[nf][1] = 0.0f; }

#pragma unroll
        for (int mf = 0; mf < 4; mf++) {
#pragma unroll
            for (int h = 0; h < 2; h++) {
                const int r = wm * 64 + mf * 16 + h * 8 + qr;
                const int rl = slr[r];
                float rs = 0.0f;
#pragma unroll
                for (int nf = 0; nf < 4; nf++) {
#pragma unroll
                    for (int e = 0; e < 2; e++) {
                        const int c = wn * 32 + nf * 8 + qc * 2 + e;
                        const float v = acc[mf][nf][h * 2 + e];
                        bool ok = (rl == slc[c]) && ((r0 + r) != (c0 + c));
                        float ex = ok ? __expf(INV_T * v) : 0.0f;
                        rs += ex;
                        colsum[nf][e] += ex;
                    }
                }
                rs += __shfl_xor_sync(0xffffffffu, rs, 1);
                rs += __shfl_xor_sync(0xffffffffu, rs, 2);
                if (qc == 0) atomicAdd(&sdenR[r], rs);
            }
        }
        if (offdiag) {
#pragma unroll
            for (int nf = 0; nf < 4; nf++) {
#pragma unroll
                for (int e = 0; e < 2; e++) {
                    float cs = colsum[nf][e];
                    cs += __shfl_xor_sync(0xffffffffu, cs, 4);
                    cs += __shfl_xor_sync(0xffffffffu, cs, 8);
                    cs += __shfl_xor_sync(0xffffffffu, cs, 16);
                    if (qr == 0) {
                        const int c = wn * 32 + nf * 8 + qc * 2 + e;
                        atomicAdd(&sdenC[c], cs);
                    }
                }
            }
        }
        __syncthreads();
        if (tid < TILE) {
            atomicAdd(&g_denom[r0 + tid], sdenR[tid]);
            if (offdiag) atomicAdd(&g_denom[c0 + tid], sdenC[tid]);
        }
        __syncthreads();   // protect sden/sl* reuse on next work item
    }

    // ---- last-block final reduction (replaces separate k_fin launch) ----
    __threadfence();
    __syncthreads();
    if (tid == 0) sdone = atomicAdd(&g_done, 1);
    __syncthreads();
    if (sdone == GEMM_GRID - 1) {
        __threadfence();   // acquire: all other blocks' g_denom adds visible
        __shared__ float red[8];
        float s = 0.0f;
#pragma unroll
        for (int j = 0; j < NB / 256; j++)
            s += __logf(g_denom[j * 256 + tid]);
#pragma unroll
        for (int off = 16; off > 0; off >>= 1)
            s += __shfl_xor_sync(0xffffffffu, s, off);
        if (lane == 0) red[wid] = s;
        __syncthreads();
        if (wid == 0) {
            float v = (lane < 8) ? red[lane] : 0.0f;
#pragma unroll
            for (int off = 4; off > 0; off >>= 1)
                v += __shfl_xor_sync(0xffffffffu, v, off);
            if (lane == 0)
                outp[0] = v / (float)NB - g_sums[1] * (2.0f * INV_T) / (float)NB;
        }
    }
}

extern "C" void kernel_launch(void* const* d_in, const int* in_sizes, int n_in,
                              void* d_out, int out_size) {
    const float* out_m  = (const float*)d_in[0];   // [2B, D]
    const float* out_1  = (const float*)d_in[1];   // [B, D]
    const float* out_2  = (const float*)d_in[2];   // [B, D]
    const int*   labels = (const int*)d_in[3];     // [2B]
    float* loss = (float*)d_out;

    cudaFuncSetAttribute(k_gemm_mma, cudaFuncAttributeMaxDynamicSharedMemorySize,
                         NSTAGE * STAGE_BYTES);

    k_sort<<<1, 1024>>>(labels);
    k_gp<<<GPB + POSB, 256>>>(out_m, out_1, out_2);
    k_gemm_mma<<<GEMM_GRID, 256, NSTAGE * STAGE_BYTES>>>(loss);
}

// round 13
// speedup vs baseline: 1.0581x; 1.0581x over previous
#include <cuda_runtime.h>
#include <cuda_bf16.h>
#include <cstdint>

// SimCLR supervised-contrastive loss, class-blocked, bf16 mma.sync GEMM.
// (tcgen05 unavailable: harness emits PTX .target sm_103 without 'a'.)
// Pipeline (3 launches):
//  k_sortpos - block 0: counting sort (smem scatter + coalesced writeback,
//              labels derived from class boundaries) + active-tile list;
//              blocks 1..64: positive-pair partial dots (overlapped).
//  k_gather  - gather rows to class-sorted bf16 order
//  k_gemm    - static-stride tile loop, cp.async 3-stage BK=64 mma.sync,
//              symmetric row+col sums; last finishing block computes the
//              final log-reduce + pos-partial sum scalar (no extra launch).

#define NB 8192
#define BHALF 4096
#define D 512
#define D4 (D/4)
#define NC 7
#define TILE 128
#define NTILE (NB/TILE)
#define NPAIR (NTILE*(NTILE+1)/2)   // 2080
#define INV_T 2.0f
#define GEMM_GRID 296
#define POSB 64

// ---- scratch (__device__ globals; no allocation) ----
__device__ __nv_bfloat16 g_Gh[NB * D];   // class-sorted rows, bf16 (8 MB)
__device__ int   g_perm[NB];
__device__ int   g_labp[NB];
__device__ float g_denom[NB];
__device__ float g_possum[POSB];
__device__ int   g_ntiles;
__device__ int   g_tiles[NPAIR];
__device__ int   g_done;    // finished-block counter for fused reduce

// ---------------------------------------------------------------------------
// k_sortpos: grid 1+POSB, 1024 threads.
// Block 0: stable counting sort of 8192 labels (7 classes) via shuffle scans.
//   Scatter goes to SHARED memory (cheap), then coalesced global writeback.
//   g_labp is piecewise constant -> filled from class boundaries, coalesced.
//   Also zeroes g_denom/g_done and builds the active-tile work list.
// Blocks 1..POSB: partial sums of dot(out_1[i], out_2[i]) -> g_possum[b-1].
__global__ __launch_bounds__(1024) void k_sortpos(const int* __restrict__ labels,
                                                  const float* __restrict__ o1,
                                                  const float* __restrict__ o2) {
    const int t = threadIdx.x, lane = t & 31, wid = t >> 5;

    if (blockIdx.x != 0) {
        // ---- positive-pair partial reduction (independent of the sort) ----
        __shared__ float red[32];
        const float4* a = reinterpret_cast<const float4*>(o1);
        const float4* v = reinterpret_cast<const float4*>(o2);
        float s = 0.0f;
        for (int i = (blockIdx.x - 1) * 1024 + t; i < BHALF * D4; i += POSB * 1024) {
            float4 x = a[i], y = v[i];
            s += x.x * y.x + x.y * y.y + x.z * y.z + x.w * y.w;
        }
#pragma unroll
        for (int off = 16; off > 0; off >>= 1)
            s += __shfl_xor_sync(0xffffffffu, s, off);
        if (lane == 0) red[wid] = s;
        __syncthreads();
        if (wid == 0) {
            float u = red[lane];
#pragma unroll
            for (int off = 16; off > 0; off >>= 1)
                u += __shfl_xor_sync(0xffffffffu, u, off);
            if (lane == 0) g_possum[blockIdx.x - 1] = u;   // plain store, no race
        }
        return;
    }

    // ---- block 0: the sort ----
    __shared__ int s_perm[NB];          // 32 KB scatter staging
    __shared__ int swtot[NC][32];
    __shared__ int swex[NC][32];
    __shared__ int sctot[NC];
    __shared__ int sbase[NC + 1];
    __shared__ int scnt;

    int lab[8];
    int cnt[NC];
#pragma unroll
    for (int c = 0; c < NC; c++) cnt[c] = 0;
#pragma unroll
    for (int j = 0; j < 8; j++) {
        lab[j] = labels[t * 8 + j];
#pragma unroll
        for (int c = 0; c < NC; c++) cnt[c] += (lab[j] == c);
    }
    // warp-inclusive scan per class
    int inc[NC];
#pragma unroll
    for (int c = 0; c < NC; c++) {
        int v = cnt[c];
#pragma unroll
        for (int off = 1; off < 32; off <<= 1) {
            int u = __shfl_up_sync(0xffffffffu, v, off);
            if (lane >= off) v += u;
        }
        inc[c] = v;
        if (lane == 31) swtot[c][wid] = v;
    }
#pragma unroll
    for (int j = 0; j < 8; j++) g_denom[t * 8 + j] = 0.0f;
    if (t == 0) { scnt = 0; g_done = 0; }
    __syncthreads();
    // cross-warp scan: warp c scans class c over the 32 warp totals
    if (wid < NC) {
        int v = swtot[wid][lane];
        int orig = v;
#pragma unroll
        for (int off = 1; off < 32; off <<= 1) {
            int u = __shfl_up_sync(0xffffffffu, v, off);
            if (lane >= off) v += u;
        }
        swex[wid][lane] = v - orig;
        if (lane == 31) sctot[wid] = v;
    }
    __syncthreads();
    if (t == 0) {
        int run = 0;
#pragma unroll
        for (int c = 0; c < NC; c++) { sbase[c] = run; run += sctot[c]; }
        sbase[NC] = run;   // == NB
    }
    __syncthreads();
    int off_[NC];
#pragma unroll
    for (int c = 0; c < NC; c++)
        off_[c] = sbase[c] + swex[c][wid] + inc[c] - cnt[c];
    // stable replay into SHARED (scattered smem stores are cheap)
#pragma unroll
    for (int j = 0; j < 8; j++) {
#pragma unroll
        for (int c = 0; c < NC; c++) {
            if (lab[j] == c) s_perm[off_[c]++] = t * 8 + j;
        }
    }
    __syncthreads();
    // coalesced writeback; g_labp derived from class boundaries
    for (int p = t; p < NB; p += 1024) {
        g_perm[p] = s_perm[p];
        int c = 0;
#pragma unroll
        for (int k = 1; k < NC; k++) c += (p >= sbase[k]);
        g_labp[p] = c;
    }

    // build active-tile list over upper-triangular (i <= j) tile pairs,
    // using class-of-boundary from sbase (no dependence on g_labp stores)
    auto classof = [&](int x) {
        int c = 0;
#pragma unroll
        for (int k = 1; k < NC; k++) c += (x >= sbase[k]);
        return c;
    };
    for (int idx = t; idx < NPAIR; idx += 1024) {
        int i = 0, rem = idx;
        while (rem >= NTILE - i) { rem -= NTILE - i; i++; }
        int j = i + rem;
        int rlo = classof(i * TILE), rhi = classof(i * TILE + TILE - 1);
        int clo = classof(j * TILE), chi = classof(j * TILE + TILE - 1);
        if (!(rhi < clo || chi < rlo)) {
            int p = atomicAdd(&scnt, 1);
            g_tiles[p] = (i << 16) | j;
        }
    }
    __syncthreads();
    if (t == 0) g_ntiles = scnt;
}

// ---------------------------------------------------------------------------
// k_gather: gather rows of `out` into class-sorted order, converting to bf16.
#define GPB 1024
__global__ void k_gather(const float* __restrict__ outm) {
    const int b = blockIdx.x, tid = threadIdx.x;
    const int n = NB * D / 8;
    for (int i = b * 256 + tid; i < n; i += GPB * 256) {
        int p = i >> 6;
        int q = i & 63;
        const float4* s =
            reinterpret_cast<const float4*>(outm + (size_t)g_perm[p] * D) + q * 2;
        float4 a = s[0], bb = s[1];
        __nv_bfloat162 h0 = __floats2bfloat162_rn(a.x, a.y);
        __nv_bfloat162 h1 = __floats2bfloat162_rn(a.z, a.w);
        __nv_bfloat162 h2 = __floats2bfloat162_rn(bb.x, bb.y);
        __nv_bfloat162 h3 = __floats2bfloat162_rn(bb.z, bb.w);
        uint4 o;
        o.x = *reinterpret_cast<uint32_t*>(&h0);
        o.y = *reinterpret_cast<uint32_t*>(&h1);
        o.z = *reinterpret_cast<uint32_t*>(&h2);
        o.w = *reinterpret_cast<uint32_t*>(&h3);
        reinterpret_cast<uint4*>(g_Gh)[i] = o;
    }
}

// ---------------------------------------------------------------------------
// mma.sync helpers
__device__ __forceinline__ uint32_t smem_u32(const void* p) {
    uint32_t a;
    asm("{ .reg .u64 t; cvta.to.shared.u64 t, %1; cvt.u32.u64 %0, t; }" : "=r"(a) : "l"(p));
    return a;
}
__device__ __forceinline__ void ldsm_x4(uint32_t* r, uint32_t addr) {
    asm volatile("ldmatrix.sync.aligned.m8n8.x4.shared.b16 {%0,%1,%2,%3}, [%4];"
                 : "=r"(r[0]), "=r"(r[1]), "=r"(r[2]), "=r"(r[3]) : "r"(addr));
}
__device__ __forceinline__ void mma16816(float* d, const uint32_t* a,
                                         uint32_t b0, uint32_t b1) {
    asm volatile(
        "mma.sync.aligned.m16n8k16.row.col.f32.bf16.bf16.f32 "
        "{%0,%1,%2,%3}, {%4,%5,%6,%7}, {%8,%9}, {%0,%1,%2,%3};"
        : "+f"(d[0]), "+f"(d[1]), "+f"(d[2]), "+f"(d[3])
        : "r"(a[0]), "r"(a[1]), "r"(a[2]), "r"(a[3]), "r"(b0), "r"(b1));
}
// 128x64-bf16 tile (128B rows). XOR swizzle: conflict-free for cp.async 16B
// stores and ldmatrix row fetches.
__device__ __forceinline__ uint32_t sw64(int row, int c16) {
    return (uint32_t)(row * 128 + ((c16 ^ (row & 7)) << 4));
}

#define BK 64
#define NKT (D / BK)          // 8
#define STAGE_BYTES 32768     // A 16KB + B 16KB per stage
#define NSTAGE 3

__global__ void __launch_bounds__(256, 2) k_gemm_mma(float* __restrict__ outp) {
    extern __shared__ char dsm[];
    __shared__ float sdenR[TILE];
    __shared__ float sdenC[TILE];
    __shared__ int   slr[TILE], slc[TILE];
    __shared__ int   sdone;

    const int tid = threadIdx.x;
    const int wid = tid >> 5, lane = tid & 31;
    const int wm = wid >> 2, wn = wid & 3;        // warp tile 64x32
    const uint4* src = reinterpret_cast<const uint4*>(g_Gh);   // 64 uint4/row
    const uint32_t dyn = smem_u32(dsm);

    const int g = lane >> 3, r8 = lane & 7;
    const int row_off = ((g & 1) << 3) + r8;
    const int cch = g >> 1;
    const int qr = lane >> 2, qc = lane & 3;
    const int ntiles = g_ntiles;

    for (int w = blockIdx.x; w < ntiles; w += GEMM_GRID) {
        const int item = g_tiles[w];
        const int r0 = (item >> 16) * TILE;
        const int c0 = (item & 0xffff) * TILE;
        const bool offdiag = (c0 != r0);

        if (tid < TILE) {
            slr[tid] = g_labp[r0 + tid];
            slc[tid] = g_labp[c0 + tid];
            sdenR[tid] = 0.0f;
            sdenC[tid] = 0.0f;
        }

        auto issue = [&](int t, int st) {
            const uint32_t sa = dyn + st * STAGE_BYTES;
#pragma unroll
            for (int j = 0; j < 4; j++) {
                int p = j * 256 + tid;
                int row = p >> 3, c16 = p & 7;
                const uint4* gA = src + (size_t)(r0 + row) * 64 + t * 8 + c16;
                const uint4* gB = src + (size_t)(c0 + row) * 64 + t * 8 + c16;
                uint32_t dA = sa + sw64(row, c16);
                uint32_t dB = sa + 16384 + sw64(row, c16);
                asm volatile("cp.async.cg.shared.global [%0], [%1], 16;\n\t"
                             "cp.async.cg.shared.global [%2], [%3], 16;"
                             :: "r"(dA), "l"(gA), "r"(dB), "l"(gB));
            }
            asm volatile("cp.async.commit_group;" ::: "memory");
        };

        issue(0, 0);
        issue(1, 1);

        float acc[4][4][4];
#pragma unroll
        for (int mf = 0; mf < 4; mf++)
#pragma unroll
            for (int nf = 0; nf < 4; nf++)
#pragma unroll
                for (int e = 0; e < 4; e++) acc[mf][nf][e] = 0.0f;

#pragma unroll
        for (int t = 0; t < NKT; t++) {
            if (t < NKT - 1) asm volatile("cp.async.wait_group 1;" ::: "memory");
            else             asm volatile("cp.async.wait_group 0;" ::: "memory");
            __syncthreads();
            if (t + 2 < NKT) issue(t + 2, (t + 2) % NSTAGE);

            const uint32_t sA = dyn + (t % NSTAGE) * STAGE_BYTES;
            const uint32_t sB = sA + 16384;
#pragma unroll
            for (int kc = 0; kc < 4; kc++) {
                uint32_t amat[4][4], bmat[2][4];
                const int c16 = kc * 2 + cch;
#pragma unroll
                for (int mf = 0; mf < 4; mf++)
                    ldsm_x4(amat[mf], sA + sw64(wm * 64 + mf * 16 + row_off, c16));
#pragma unroll
                for (int nb = 0; nb < 2; nb++)
                    ldsm_x4(bmat[nb], sB + sw64(wn * 32 + nb * 16 + row_off, c16));
#pragma unroll
                for (int mf = 0; mf < 4; mf++)
#pragma unroll
                    for (int nf = 0; nf < 4; nf++)
                        mma16816(acc[mf][nf], amat[mf],
                                 bmat[nf >> 1][nf & 1], bmat[nf >> 1][2 + (nf & 1)]);
            }
        }

        // ---- epilogue: mask + exp; row sums always, col sums if offdiag ----
        float colsum[4][2];
#pragma unroll
        for (int nf = 0; nf < 4; nf++) { colsum[nf][0] = 0.0f; colsum[nf][1] = 0.0f; }

#pragma unroll
        for (int mf = 0; mf < 4; mf++) {
#pragma unroll
            for (int h = 0; h < 2; h++) {
                const int r = wm * 64 + mf * 16 + h * 8 + qr;
                const int rl = slr[r];
                float rs = 0.0f;
#pragma unroll
                for (int nf = 0; nf < 4; nf++) {
#pragma unroll
                    for (int e = 0; e < 2; e++) {
                        const int c = wn * 32 + nf * 8 + qc * 2 + e;
                        const float v = acc[mf][nf][h * 2 + e];
                        bool ok = (rl == slc[c]) && ((r0 + r) != (c0 + c));
                        float ex = ok ? __expf(INV_T * v) : 0.0f;
                        rs += ex;
                        colsum[nf][e] += ex;
                    }
                }
                rs += __shfl_xor_sync(0xffffffffu, rs, 1);
                rs += __shfl_xor_sync(0xffffffffu, rs, 2);
                if (qc == 0) atomicAdd(&sdenR[r], rs);
            }
        }
        if (offdiag) {
#pragma unroll
            for (int nf = 0; nf < 4; nf++) {
#pragma unroll
                for (int e = 0; e < 2; e++) {
                    float cs = colsum[nf][e];
                    cs += __shfl_xor_sync(0xffffffffu, cs, 4);
                    cs += __shfl_xor_sync(0xffffffffu, cs, 8);
                    cs += __shfl_xor_sync(0xffffffffu, cs, 16);
                    if (qr == 0) {
                        const int c = wn * 32 + nf * 8 + qc * 2 + e;
                        atomicAdd(&sdenC[c], cs);
                    }
                }
            }
        }
        __syncthreads();
        if (tid < TILE) {
            atomicAdd(&g_denom[r0 + tid], sdenR[tid]);
            if (offdiag) atomicAdd(&g_denom[c0 + tid], sdenC[tid]);
        }
        __syncthreads();   // protect sden/sl* reuse on next work item
    }

    // ---- last-block final reduction (no separate kernel launch) ----
    __threadfence();
    __syncthreads();
    if (tid == 0) sdone = atomicAdd(&g_done, 1);
    __syncthreads();
    if (sdone == GEMM_GRID - 1) {
        __threadfence();   // acquire: all other blocks' g_denom adds visible
        __shared__ float red[8];
        float s = 0.0f;
#pragma unroll
        for (int j = 0; j < NB / 256; j++)
            s += __logf(g_denom[j * 256 + tid]);
#pragma unroll
        for (int off = 16; off > 0; off >>= 1)
            s += __shfl_xor_sync(0xffffffffu, s, off);
        if (lane == 0) red[wid] = s;
        __syncthreads();
        if (wid == 0) {
            float v = (lane < 8) ? red[lane] : 0.0f;
#pragma unroll
            for (int off = 4; off > 0; off >>= 1)
                v += __shfl_xor_sync(0xffffffffu, v, off);
            // pos partial sum: lane-parallel over POSB slots
            float ps = g_possum[lane] + g_possum[lane + 32];
#pragma unroll
            for (int off = 16; off > 0; off >>= 1)
                ps += __shfl_xor_sync(0xffffffffu, ps, off);
            if (lane == 0)
                outp[0] = v / (float)NB - ps * (2.0f * INV_T) / (float)NB;
        }
    }
}

extern "C" void kernel_launch(void* const* d_in, const int* in_sizes, int n_in,
                              void* d_out, int out_size) {
    const float* out_m  = (const float*)d_in[0];   // [2B, D]
    const float* out_1  = (const float*)d_in[1];   // [B, D]
    const float* out_2  = (const float*)d_in[2];   // [B, D]
    const int*   labels = (const int*)d_in[3];     // [2B]
    float* loss = (float*)d_out;

    cudaFuncSetAttribute(k_gemm_mma, cudaFuncAttributeMaxDynamicSharedMemorySize,
                         NSTAGE * STAGE_BYTES);

    k_sortpos<<<1 + POSB, 1024>>>(labels, out_1, out_2);
    k_gather<<<GPB, 256>>>(out_m);
    k_gemm_mma<<<GEMM_GRID, 256, NSTAGE * STAGE_BYTES>>>(loss);
}